// round 1
// baseline (speedup 1.0000x reference)
#include <cuda_runtime.h>
#include <math.h>

#define SS 8
#define TT 2048
#define BB 8
#define DD 64
#define KK 512
#define NTOK (BB*TT)        // 16384
#define TPB 64              // tokens per block
#define CHUNK 128           // codes per chunk
#define NCHUNK (KK/CHUNK)   // 4
#define ZQ_OFF 0
#define ZE_OFF (NTOK*DD)          // 1048576
#define ZK_OFF (2*NTOK*DD)        // 2097152

__device__ float g_Enorm[SS*KK];

// ||E[s,k]||^2, replicating reference rounding: square (rounded), then add (rounded)
__global__ void enorm_kernel(const float* __restrict__ E) {
    int i = blockIdx.x * blockDim.x + threadIdx.x;   // s*K + k
    if (i < SS*KK) {
        const float* e = E + (size_t)i * DD;
        float s = 0.f;
        #pragma unroll 8
        for (int d = 0; d < DD; ++d)
            s = __fadd_rn(s, __fmul_rn(e[d], e[d]));
        g_Enorm[i] = s;
    }
}

struct SmemT {
    float x_t[DD][TPB];      // x transposed [d][tok]
    float z_sm[DD][TPB];     // z transposed [d][tok]
    float E_t[DD][CHUNK];    // E chunk transposed [d][code]
    float W_sm[DD][DD];      // [d][e]
    float att[TPB][DD+1];
    float ze[TPB][DD+1];
    float zq[TPB][DD+1];
    float red_val[TPB][17];
    int   red_idx[TPB][17];
    float En[CHUNK];
    float znorm[TPB];
    int   kmin[TPB];
};

__global__ __launch_bounds__(256, 1)
void qlayer_kernel(const float* __restrict__ x,
                   const float* __restrict__ W,
                   const float* __restrict__ bias,
                   const float* __restrict__ gamma,
                   const float* __restrict__ beta,
                   const float* __restrict__ bn_mean,
                   const float* __restrict__ bn_var,
                   const float* __restrict__ E,
                   float* __restrict__ out)
{
    extern __shared__ char smem_raw[];
    SmemT* sm = reinterpret_cast<SmemT*>(smem_raw);

    const int tid  = threadIdx.x;
    const int tok0 = blockIdx.x * TPB;

    // ---- load x tile transposed: t = tid&63 owns one token row ----
    {
        const int t = tid & 63, dg = tid >> 6;     // dg in 0..3, 16 d's each
        const float* xp = x + (size_t)(tok0 + t) * DD + dg * 16;
        #pragma unroll
        for (int j = 0; j < 4; ++j) {
            float4 v = *(const float4*)(xp + j * 4);
            int d = dg * 16 + j * 4;
            sm->x_t[d+0][t] = v.x; sm->x_t[d+1][t] = v.y;
            sm->x_t[d+2][t] = v.z; sm->x_t[d+3][t] = v.w;
        }
    }
    for (int i = tid; i < TPB*(DD+1); i += 256) {
        ((float*)sm->ze)[i] = 0.f;
        ((float*)sm->zq)[i] = 0.f;
    }
    __syncthreads();

    const int ty = tid >> 4;    // 0..15 : token group (4 tokens)
    const int tx = tid & 15;    // 0..15 : e-group (proj) / code group (8 codes)

    for (int s = 0; s < SS; ++s) {
        // ---- load W[s] ----
        for (int i = tid; i < DD*DD; i += 256)
            ((float*)sm->W_sm)[i] = W[s*DD*DD + i];
        __syncthreads();

        // ---- proj GEMM: 4 tokens x 4 e per thread ----
        {
            float acc[4][4] = {};
            #pragma unroll 8
            for (int d = 0; d < DD; ++d) {
                float4 xv = *(const float4*)&sm->x_t[d][ty*4];
                float4 wv = *(const float4*)&sm->W_sm[d][tx*4];
                float xx[4] = {xv.x, xv.y, xv.z, xv.w};
                float ww[4] = {wv.x, wv.y, wv.z, wv.w};
                #pragma unroll
                for (int i = 0; i < 4; ++i)
                    #pragma unroll
                    for (int j = 0; j < 4; ++j)
                        acc[i][j] = fmaf(xx[i], ww[j], acc[i][j]);
            }
            // BN, replicating reference op order:
            // bn = ((gamma * (proj - mean)) * inv) + beta ;  proj = dot + b
            #pragma unroll
            for (int j = 0; j < 4; ++j) {
                int e = tx*4 + j;
                float inv = 1.0f / sqrtf(__fadd_rn(bn_var[s*DD+e], 1e-3f));
                float g  = gamma[s*DD+e];
                float bt = beta[s*DD+e];
                float mn = bn_mean[s*DD+e];
                float bi = bias[s*DD+e];
                #pragma unroll
                for (int i = 0; i < 4; ++i) {
                    float p = __fadd_rn(acc[i][j], bi);
                    float v = __fadd_rn(__fmul_rn(__fmul_rn(g, __fsub_rn(p, mn)), inv), bt);
                    sm->att[ty*4+i][e] = v;
                }
            }
        }
        __syncthreads();

        // ---- softmax + z (+ z_e accumulate, ||z||^2), one thread per token ----
        if (tid < TPB) {
            const int t = tid;
            float m = -INFINITY;
            #pragma unroll 8
            for (int e = 0; e < DD; ++e) m = fmaxf(m, sm->att[t][e]);
            float sum = 0.f;
            #pragma unroll 8
            for (int e = 0; e < DD; ++e) {
                float v = expf(sm->att[t][e] - m);
                sm->att[t][e] = v;
                sum = __fadd_rn(sum, v);
            }
            float zn = 0.f;
            #pragma unroll 8
            for (int e = 0; e < DD; ++e) {
                float a = __fdiv_rn(sm->att[t][e], sum);         // true division, as ref
                float z = __fmul_rn(sm->x_t[e][t], a);
                sm->z_sm[e][t] = z;
                sm->ze[t][e] = __fadd_rn(sm->ze[t][e], z);
                zn = __fadd_rn(zn, __fmul_rn(z, z));
            }
            sm->znorm[t] = zn;
        }
        __syncthreads();

        // ---- codebook distance GEMM + fused argmin ----
        float best_v[4];
        int   best_i[4];
        #pragma unroll
        for (int i = 0; i < 4; ++i) { best_v[i] = INFINITY; best_i[i] = 0x7fffffff; }

        for (int c = 0; c < NCHUNK; ++c) {
            // load E chunk transposed (conflict-free smem writes)
            {
                const int kk = tid & 127, dg = tid >> 7;   // dg 0..1, 32 d's each
                const float* ep = E + ((size_t)s*KK + c*CHUNK + kk) * DD + dg*32;
                #pragma unroll
                for (int j = 0; j < 8; ++j) {
                    float4 v = *(const float4*)(ep + j * 4);
                    int d = dg*32 + j*4;
                    sm->E_t[d+0][kk] = v.x; sm->E_t[d+1][kk] = v.y;
                    sm->E_t[d+2][kk] = v.z; sm->E_t[d+3][kk] = v.w;
                }
                if (dg == 0) sm->En[kk] = g_Enorm[s*KK + c*CHUNK + kk];
            }
            __syncthreads();

            float sacc[4][8] = {};
            #pragma unroll 4
            for (int d = 0; d < DD; ++d) {
                float4 zv = *(const float4*)&sm->z_sm[d][ty*4];
                float4 ea = *(const float4*)&sm->E_t[d][tx*8];
                float4 eb = *(const float4*)&sm->E_t[d][tx*8+4];
                float zz[4] = {zv.x, zv.y, zv.z, zv.w};
                float ee[8] = {ea.x, ea.y, ea.z, ea.w, eb.x, eb.y, eb.z, eb.w};
                #pragma unroll
                for (int i = 0; i < 4; ++i)
                    #pragma unroll
                    for (int j = 0; j < 8; ++j)
                        sacc[i][j] = fmaf(zz[i], ee[j], sacc[i][j]);
            }

            #pragma unroll
            for (int i = 0; i < 4; ++i) {
                float zn = sm->znorm[ty*4+i];
                #pragma unroll
                for (int j = 0; j < 8; ++j) {
                    // d2 = (||z||^2 - 2*dot) + ||E||^2  (reference association)
                    float v = __fadd_rn(__fsub_rn(zn, 2.0f * sacc[i][j]),
                                        sm->En[tx*8+j]);
                    int code = c*CHUNK + tx*8 + j;
                    if (v < best_v[i]) { best_v[i] = v; best_i[i] = code; }
                }
            }
            __syncthreads();
        }

        // cross-thread argmin reduction (first-occurrence tie-break via min idx)
        #pragma unroll
        for (int i = 0; i < 4; ++i) {
            sm->red_val[ty*4+i][tx] = best_v[i];
            sm->red_idx[ty*4+i][tx] = best_i[i];
        }
        __syncthreads();
        if (tid < TPB) {
            const int t = tid;
            float bv = sm->red_val[t][0];
            int   bi = sm->red_idx[t][0];
            #pragma unroll
            for (int j = 1; j < 16; ++j) {
                float v = sm->red_val[t][j];
                int  ii = sm->red_idx[t][j];
                if (v < bv || (v == bv && ii < bi)) { bv = v; bi = ii; }
            }
            sm->kmin[t] = bi;
            out[ZK_OFF + (size_t)s*NTOK + tok0 + t] = (float)bi;
        }
        __syncthreads();

        // gather E[s, kmin] into z_q accumulator
        {
            const int t = tid >> 2, dg = tid & 3;
            const float* ep = E + ((size_t)s*KK + sm->kmin[t]) * DD + dg*16;
            #pragma unroll
            for (int j = 0; j < 4; ++j) {
                float4 v = *(const float4*)(ep + j * 4);
                int d = dg*16 + j*4;
                sm->zq[t][d+0] = __fadd_rn(sm->zq[t][d+0], v.x);
                sm->zq[t][d+1] = __fadd_rn(sm->zq[t][d+1], v.y);
                sm->zq[t][d+2] = __fadd_rn(sm->zq[t][d+2], v.z);
                sm->zq[t][d+3] = __fadd_rn(sm->zq[t][d+3], v.w);
            }
        }
        __syncthreads();
    } // s

    // ---- write z_q, z_e (coalesced) ----
    for (int i = tid; i < TPB*DD; i += 256) {
        int t = i >> 6, d = i & 63;
        out[ZQ_OFF + (size_t)(tok0 + t) * DD + d] = sm->zq[t][d];
        out[ZE_OFF + (size_t)(tok0 + t) * DD + d] = sm->ze[t][d];
    }
}

extern "C" void kernel_launch(void* const* d_in, const int* in_sizes, int n_in,
                              void* d_out, int out_size)
{
    const float* x       = (const float*)d_in[0];
    const float* W       = (const float*)d_in[1];
    const float* b       = (const float*)d_in[2];
    const float* gamma   = (const float*)d_in[3];
    const float* beta    = (const float*)d_in[4];
    const float* bn_mean = (const float*)d_in[5];
    const float* bn_var  = (const float*)d_in[6];
    const float* E       = (const float*)d_in[7];
    float* out = (float*)d_out;

    enorm_kernel<<<(SS*KK + 255)/256, 256>>>(E);

    const int smem = (int)sizeof(SmemT);
    cudaFuncSetAttribute(qlayer_kernel,
                         cudaFuncAttributeMaxDynamicSharedMemorySize, smem);
    qlayer_kernel<<<NTOK/TPB, 256, smem>>>(x, W, b, gamma, beta,
                                           bn_mean, bn_var, E, out);
}

// round 3
// speedup vs baseline: 1.6256x; 1.6256x over previous
#include <cuda_runtime.h>
#include <math.h>

#define SS 8
#define TT 2048
#define BB 8
#define DD 64
#define KK 512
#define NTOK (BB*TT)        // 16384
#define TPB 64              // tokens per block
#define CHUNK 128           // codes per chunk
#define NCHUNK (KK/CHUNK)   // 4
#define ZQ_OFF 0
#define ZE_OFF (NTOK*DD)          // 1048576
#define ZK_OFF (2*NTOK*DD)        // 2097152

typedef unsigned long long ULL;

__device__ float g_Enorm[SS*KK];
// E pre-packed: [s][chunk][d][pair] with pair p = (E[2p][d], E[2p+1][d])
__device__ __align__(16) float2 g_Epack[SS*NCHUNK*DD*(CHUNK/2)];

__device__ __forceinline__ void fma2(ULL& d, ULL a, ULL b) {
    asm("fma.rn.f32x2 %0, %1, %2, %3;" : "=l"(d) : "l"(a), "l"(b), "l"(d));
}
__device__ __forceinline__ float2 unpk(ULL v) {
    float lo, hi;
    asm("mov.b64 {%0,%1}, %2;" : "=f"(lo), "=f"(hi) : "l"(v));
    return make_float2(lo, hi);
}

// ||E[s,k]||^2 with reference rounding: square (rounded), then add (rounded)
__global__ void enorm_kernel(const float* __restrict__ E) {
    int i = blockIdx.x * blockDim.x + threadIdx.x;
    if (i < SS*KK) {
        const float* e = E + (size_t)i * DD;
        float s = 0.f;
        #pragma unroll 8
        for (int d = 0; d < DD; ++d)
            s = __fadd_rn(s, __fmul_rn(e[d], e[d]));
        g_Enorm[i] = s;
    }
}

// transpose + pair-pack E for conflict-free f32x2 smem loads
__global__ void epack_kernel(const float* __restrict__ E) {
    int idx = blockIdx.x * blockDim.x + threadIdx.x;   // over S*4*64*64
    if (idx < SS*NCHUNK*DD*(CHUNK/2)) {
        int p = idx & 63;
        int d = (idx >> 6) & 63;
        int c = (idx >> 12) & (NCHUNK-1);
        int s = idx >> 14;
        const float* base = E + ((size_t)s*KK + c*CHUNK) * DD;
        g_Epack[idx] = make_float2(base[(2*p)*DD + d], base[(2*p+1)*DD + d]);
    }
}

// smem: x_dup 32768 | z_dup 32768 | region 33024 (W 16384 + att 16640, aliased by E_p 32768)
//       | En 512 | znorm 256 | kmin 256  = 99584 bytes
#define SMEM_BYTES 99584

__global__ __launch_bounds__(256, 2)
void qlayer_kernel(const float* __restrict__ x,
                   const float* __restrict__ W,
                   const float* __restrict__ bias,
                   const float* __restrict__ gamma,
                   const float* __restrict__ beta,
                   const float* __restrict__ bn_mean,
                   const float* __restrict__ bn_var,
                   const float* __restrict__ E,
                   float* __restrict__ out)
{
    extern __shared__ char smraw[];
    float2 (*x_dup)[TPB] = (float2(*)[TPB])smraw;                   // [d][t] dup
    float2 (*z_dup)[TPB] = (float2(*)[TPB])(smraw + 32768);         // [d][t] dup
    char*  region        = smraw + 65536;
    float  (*W_sm)[DD]   = (float(*)[DD])region;                    // [d][e]
    float  (*att)[DD+1]  = (float(*)[DD+1])(region + 16384);        // [t][e]
    float2 (*E_p)[CHUNK/2] = (float2(*)[CHUNK/2])region;            // [d][pair] (aliases W+att)
    float* En    = (float*)(smraw + 65536 + 33024);                 // [128]
    float* znorm = En + CHUNK;                                      // [64]
    int*   kmin  = (int*)(znorm + TPB);                             // [64]

    const int tid  = threadIdx.x;
    const int tok0 = blockIdx.x * TPB;

    // ---- load x tile, duplicated-transposed ----
    {
        const int t = tid & 63, dg = tid >> 6;     // dg 0..3
        const float* xp = x + (size_t)(tok0 + t) * DD + dg * 16;
        #pragma unroll
        for (int j = 0; j < 4; ++j) {
            float4 v = *(const float4*)(xp + j * 4);
            int d = dg * 16 + j * 4;
            x_dup[d+0][t] = make_float2(v.x, v.x);
            x_dup[d+1][t] = make_float2(v.y, v.y);
            x_dup[d+2][t] = make_float2(v.z, v.z);
            x_dup[d+3][t] = make_float2(v.w, v.w);
        }
    }

    float ze_reg[16], zq_reg[16];
    #pragma unroll
    for (int j = 0; j < 16; ++j) { ze_reg[j] = 0.f; zq_reg[j] = 0.f; }

    __syncthreads();

    for (int s = 0; s < SS; ++s) {
        // ---- A) load W (region is free: previous E_p reads are behind a sync) ----
        for (int i = tid; i < DD*DD; i += 256)
            ((float*)W_sm)[i] = W[s*DD*DD + i];
        __syncthreads();

        // ---- B) proj GEMM (f32x2): 4 tokens x 4 e per thread ----
        {
            const int ty = tid >> 4, tx = tid & 15;
            ULL a00=0,a01=0,a10=0,a11=0,a20=0,a21=0,a30=0,a31=0;
            #pragma unroll 8
            for (int d = 0; d < DD; ++d) {
                ulonglong2 xa = *(const ulonglong2*)&x_dup[d][ty*4];
                ulonglong2 xb = *(const ulonglong2*)&x_dup[d][ty*4+2];
                ulonglong2 wv = *(const ulonglong2*)&W_sm[d][tx*4];
                fma2(a00, xa.x, wv.x); fma2(a01, xa.x, wv.y);
                fma2(a10, xa.y, wv.x); fma2(a11, xa.y, wv.y);
                fma2(a20, xb.x, wv.x); fma2(a21, xb.x, wv.y);
                fma2(a30, xb.y, wv.x); fma2(a31, xb.y, wv.y);
            }
            // BN, reference op order
            float4 bi4 = *(const float4*)&bias[s*DD + tx*4];
            float4 gm4 = *(const float4*)&gamma[s*DD + tx*4];
            float4 bt4 = *(const float4*)&beta[s*DD + tx*4];
            float4 mn4 = *(const float4*)&bn_mean[s*DD + tx*4];
            float4 vr4 = *(const float4*)&bn_var[s*DD + tx*4];
            float inv0 = 1.0f / sqrtf(__fadd_rn(vr4.x, 1e-3f));
            float inv1 = 1.0f / sqrtf(__fadd_rn(vr4.y, 1e-3f));
            float inv2 = 1.0f / sqrtf(__fadd_rn(vr4.z, 1e-3f));
            float inv3 = 1.0f / sqrtf(__fadd_rn(vr4.w, 1e-3f));
            ULL accs[4][2] = {{a00,a01},{a10,a11},{a20,a21},{a30,a31}};
            #pragma unroll
            for (int i = 0; i < 4; ++i) {
                float2 p0 = unpk(accs[i][0]);
                float2 p1 = unpk(accs[i][1]);
                float* row = att[ty*4+i];
                float pv;
                pv = __fadd_rn(p0.x, bi4.x);
                row[tx*4+0] = __fadd_rn(__fmul_rn(__fmul_rn(gm4.x, __fsub_rn(pv, mn4.x)), inv0), bt4.x);
                pv = __fadd_rn(p0.y, bi4.y);
                row[tx*4+1] = __fadd_rn(__fmul_rn(__fmul_rn(gm4.y, __fsub_rn(pv, mn4.y)), inv1), bt4.y);
                pv = __fadd_rn(p1.x, bi4.z);
                row[tx*4+2] = __fadd_rn(__fmul_rn(__fmul_rn(gm4.z, __fsub_rn(pv, mn4.z)), inv2), bt4.z);
                pv = __fadd_rn(p1.y, bi4.w);
                row[tx*4+3] = __fadd_rn(__fmul_rn(__fmul_rn(gm4.w, __fsub_rn(pv, mn4.w)), inv3), bt4.w);
            }
        }
        __syncthreads();

        // ---- C) softmax + z (4 threads / token) ----
        {
            const int t = tid >> 2, q = tid & 3;
            float ev[16];
            float m = -INFINITY;
            #pragma unroll
            for (int j = 0; j < 16; ++j) { ev[j] = att[t][q*16 + j]; m = fmaxf(m, ev[j]); }
            m = fmaxf(m, __shfl_xor_sync(0xffffffffu, m, 1));
            m = fmaxf(m, __shfl_xor_sync(0xffffffffu, m, 2));
            float sum = 0.f;
            #pragma unroll
            for (int j = 0; j < 16; ++j) { ev[j] = expf(ev[j] - m); sum = __fadd_rn(sum, ev[j]); }
            sum = __fadd_rn(sum, __shfl_xor_sync(0xffffffffu, sum, 1));
            sum = __fadd_rn(sum, __shfl_xor_sync(0xffffffffu, sum, 2));
            float zn = 0.f;
            #pragma unroll
            for (int j = 0; j < 16; ++j) {
                float a = __fdiv_rn(ev[j], sum);
                float xx = x_dup[q*16 + j][t].x;
                float z = __fmul_rn(xx, a);
                z_dup[q*16 + j][t] = make_float2(z, z);
                ze_reg[j] = __fadd_rn(ze_reg[j], z);
                zn = __fadd_rn(zn, __fmul_rn(z, z));
            }
            zn = __fadd_rn(zn, __shfl_xor_sync(0xffffffffu, zn, 1));
            zn = __fadd_rn(zn, __shfl_xor_sync(0xffffffffu, zn, 2));
            if (q == 0) znorm[t] = zn;
        }
        __syncthreads();    // z ready; att/W dead -> region reusable as E_p

        // ---- D) codebook distance (f32x2): 8 tokens x 4 codes per thread ----
        const int w = tid >> 5, l = tid & 31;
        float best_v[8]; int best_i[8];
        #pragma unroll
        for (int i = 0; i < 8; ++i) { best_v[i] = INFINITY; best_i[i] = 0x7fffffff; }

        for (int c = 0; c < NCHUNK; ++c) {
            // fill E_p linearly from pre-packed global (coalesced, conflict-free)
            {
                const float4* src = (const float4*)(g_Epack + ((s*NCHUNK + c) << 12));
                float4* dst = (float4*)E_p;
                #pragma unroll
                for (int i = tid; i < 2048; i += 256) dst[i] = src[i];
                if (tid < CHUNK) En[tid] = g_Enorm[s*KK + c*CHUNK + tid];
            }
            __syncthreads();

            ULL acc[8][2];
            #pragma unroll
            for (int i = 0; i < 8; ++i) { acc[i][0] = 0ull; acc[i][1] = 0ull; }

            #pragma unroll 16
            for (int d = 0; d < DD; ++d) {
                ulonglong2 z0 = *(const ulonglong2*)&z_dup[d][w*8+0];
                ulonglong2 z1 = *(const ulonglong2*)&z_dup[d][w*8+2];
                ulonglong2 z2 = *(const ulonglong2*)&z_dup[d][w*8+4];
                ulonglong2 z3 = *(const ulonglong2*)&z_dup[d][w*8+6];
                ULL e0 = *(const ULL*)&E_p[d][l];
                ULL e1 = *(const ULL*)&E_p[d][l+32];
                fma2(acc[0][0], z0.x, e0); fma2(acc[0][1], z0.x, e1);
                fma2(acc[1][0], z0.y, e0); fma2(acc[1][1], z0.y, e1);
                fma2(acc[2][0], z1.x, e0); fma2(acc[2][1], z1.x, e1);
                fma2(acc[3][0], z1.y, e0); fma2(acc[3][1], z1.y, e1);
                fma2(acc[4][0], z2.x, e0); fma2(acc[4][1], z2.x, e1);
                fma2(acc[5][0], z2.y, e0); fma2(acc[5][1], z2.y, e1);
                fma2(acc[6][0], z3.x, e0); fma2(acc[6][1], z3.x, e1);
                fma2(acc[7][0], z3.y, e0); fma2(acc[7][1], z3.y, e1);
            }

            // epilogue: d2 = (||z||^2 - 2*dot) + ||E||^2 (reference association)
            float2 en0 = *(const float2*)&En[2*l];
            float2 en1 = *(const float2*)&En[2*l + 64];
            const int cb = c*CHUNK;
            #pragma unroll
            for (int i = 0; i < 8; ++i) {
                float zn = znorm[w*8 + i];
                float2 d0 = unpk(acc[i][0]);
                float2 d1 = unpk(acc[i][1]);
                float v;
                v = __fadd_rn(__fsub_rn(zn, 2.0f*d0.x), en0.x);
                if (v < best_v[i]) { best_v[i] = v; best_i[i] = cb + 2*l; }
                v = __fadd_rn(__fsub_rn(zn, 2.0f*d0.y), en0.y);
                if (v < best_v[i]) { best_v[i] = v; best_i[i] = cb + 2*l + 1; }
                v = __fadd_rn(__fsub_rn(zn, 2.0f*d1.x), en1.x);
                if (v < best_v[i]) { best_v[i] = v; best_i[i] = cb + 2*l + 64; }
                v = __fadd_rn(__fsub_rn(zn, 2.0f*d1.y), en1.y);
                if (v < best_v[i]) { best_v[i] = v; best_i[i] = cb + 2*l + 65; }
            }
            __syncthreads();    // before next chunk overwrites E_p
        }

        // ---- E) warp argmin reduction (first-occurrence => min index tie-break) ----
        #pragma unroll
        for (int i = 0; i < 8; ++i) {
            float v = best_v[i]; int bi = best_i[i];
            #pragma unroll
            for (int off = 16; off > 0; off >>= 1) {
                float ov = __shfl_xor_sync(0xffffffffu, v, off);
                int   oi = __shfl_xor_sync(0xffffffffu, bi, off);
                if (ov < v || (ov == v && oi < bi)) { v = ov; bi = oi; }
            }
            if (l == i) {
                kmin[w*8 + i] = bi;
                out[ZK_OFF + (size_t)s*NTOK + tok0 + w*8 + i] = (float)bi;
            }
        }
        __syncthreads();

        // ---- F) gather E[s, kmin] into z_q registers ----
        {
            const int t = tid >> 2, q = tid & 3;
            const int k = kmin[t];
            const float* ep = E + ((size_t)s*KK + k) * DD + q*16;
            #pragma unroll
            for (int j4 = 0; j4 < 4; ++j4) {
                float4 v = *(const float4*)(ep + 4*j4);
                zq_reg[4*j4+0] = __fadd_rn(zq_reg[4*j4+0], v.x);
                zq_reg[4*j4+1] = __fadd_rn(zq_reg[4*j4+1], v.y);
                zq_reg[4*j4+2] = __fadd_rn(zq_reg[4*j4+2], v.z);
                zq_reg[4*j4+3] = __fadd_rn(zq_reg[4*j4+3], v.w);
            }
        }
        __syncthreads();
    } // s

    // ---- write z_q, z_e ----
    {
        const int t = tid >> 2, q = tid & 3;
        float* oq = out + ZQ_OFF + (size_t)(tok0 + t) * DD + q*16;
        float* oe = out + ZE_OFF + (size_t)(tok0 + t) * DD + q*16;
        #pragma unroll
        for (int j4 = 0; j4 < 4; ++j4) {
            *(float4*)(oq + 4*j4) = make_float4(zq_reg[4*j4], zq_reg[4*j4+1],
                                                zq_reg[4*j4+2], zq_reg[4*j4+3]);
            *(float4*)(oe + 4*j4) = make_float4(ze_reg[4*j4], ze_reg[4*j4+1],
                                                ze_reg[4*j4+2], ze_reg[4*j4+3]);
        }
    }
}

extern "C" void kernel_launch(void* const* d_in, const int* in_sizes, int n_in,
                              void* d_out, int out_size)
{
    const float* x       = (const float*)d_in[0];
    const float* W       = (const float*)d_in[1];
    const float* b       = (const float*)d_in[2];
    const float* gamma   = (const float*)d_in[3];
    const float* beta    = (const float*)d_in[4];
    const float* bn_mean = (const float*)d_in[5];
    const float* bn_var  = (const float*)d_in[6];
    const float* E       = (const float*)d_in[7];
    float* out = (float*)d_out;

    enorm_kernel<<<(SS*KK + 255)/256, 256>>>(E);
    epack_kernel<<<(SS*NCHUNK*DD*(CHUNK/2) + 255)/256, 256>>>(E);

    cudaFuncSetAttribute(qlayer_kernel,
                         cudaFuncAttributeMaxDynamicSharedMemorySize, SMEM_BYTES);
    qlayer_kernel<<<NTOK/TPB, 256, SMEM_BYTES>>>(x, W, b, gamma, beta,
                                                 bn_mean, bn_var, E, out);
}

// round 4
// speedup vs baseline: 1.7236x; 1.0603x over previous
#include <cuda_runtime.h>
#include <math.h>

#define SS 8
#define TT 2048
#define BB 8
#define DD 64
#define KK 512
#define NTOK (BB*TT)        // 16384
#define TPB 64              // tokens per block
#define CHUNK 128           // codes per chunk
#define NCHUNK (KK/CHUNK)   // 4
#define ZQ_OFF 0
#define ZE_OFF (NTOK*DD)          // 1048576
#define ZK_OFF (2*NTOK*DD)        // 2097152
#define NPACK (SS*NCHUNK*DD*(CHUNK/2))   // 131072

typedef unsigned long long ULL;

__device__ float g_Enorm[SS*KK];
// E pre-packed: [s][chunk][d][pair] with pair p = (E[2p][d], E[2p+1][d])
__device__ __align__(16) float2 g_Epack[NPACK];
// per-slot z scratch: [s][token][d]  (32 MB)
__device__ __align__(16) float g_z[(size_t)SS*NTOK*DD];

__device__ __forceinline__ void fma2(ULL& d, ULL a, ULL b) {
    asm("fma.rn.f32x2 %0, %1, %2, %3;" : "=l"(d) : "l"(a), "l"(b), "l"(d));
}
__device__ __forceinline__ float2 unpk(ULL v) {
    float lo, hi;
    asm("mov.b64 {%0,%1}, %2;" : "=f"(lo), "=f"(hi) : "l"(v));
    return make_float2(lo, hi);
}

// ---- merged prep: blocks [0,512) pack E; blocks [512,528) compute norms ----
// norm keeps the exact sequential d-order rounding of the reference-matched enorm.
__global__ void prep_kernel(const float* __restrict__ E) {
    int gid = blockIdx.x * blockDim.x + threadIdx.x;
    if (gid < NPACK) {
        int p = gid & 63;
        int d = (gid >> 6) & 63;
        int c = (gid >> 12) & (NCHUNK-1);
        int s = gid >> 14;
        const float* base = E + ((size_t)s*KK + c*CHUNK) * DD;
        g_Epack[gid] = make_float2(base[(2*p)*DD + d], base[(2*p+1)*DD + d]);
    } else {
        int i = gid - NPACK;            // row index s*K + k
        if (i < SS*KK) {
            const float* e = E + (size_t)i * DD;
            float s = 0.f;
            #pragma unroll 8
            for (int d = 0; d < DD; ++d)
                s = __fadd_rn(s, __fmul_rn(e[d], e[d]));
            g_Enorm[i] = s;
        }
    }
}

// smem: x_dup 32768 | z_dup 32768 | region 33024 (W 16384 + att 16640, aliased by E_p 32768)
//       | En 512 | znorm 256 | kmin 256  = 99584 bytes
#define SMEM_BYTES 99584

__global__ __launch_bounds__(256, 2)
void qlayer_k1(const float* __restrict__ x,
               const float* __restrict__ W,
               const float* __restrict__ bias,
               const float* __restrict__ gamma,
               const float* __restrict__ beta,
               const float* __restrict__ bn_mean,
               const float* __restrict__ bn_var,
               float* __restrict__ out)
{
    extern __shared__ char smraw[];
    float2 (*x_dup)[TPB] = (float2(*)[TPB])smraw;                   // [d][t] dup
    float2 (*z_dup)[TPB] = (float2(*)[TPB])(smraw + 32768);         // [d][t] dup
    char*  region        = smraw + 65536;
    float  (*W_sm)[DD]   = (float(*)[DD])region;                    // [d][e]
    float  (*att)[DD+1]  = (float(*)[DD+1])(region + 16384);        // [t][e]
    float2 (*E_p)[CHUNK/2] = (float2(*)[CHUNK/2])region;            // [d][pair]
    float* En    = (float*)(smraw + 65536 + 33024);                 // [128]
    float* znorm = En + CHUNK;                                      // [64]
    int*   kmin  = (int*)(znorm + TPB);                             // [64]

    const int tid  = threadIdx.x;
    const int tok0 = blockIdx.x * TPB;
    const int s    = blockIdx.y;

    // ---- load x tile, duplicated-transposed; W in parallel ----
    {
        const int t = tid & 63, dg = tid >> 6;     // dg 0..3
        const float* xp = x + (size_t)(tok0 + t) * DD + dg * 16;
        #pragma unroll
        for (int j = 0; j < 4; ++j) {
            float4 v = *(const float4*)(xp + j * 4);
            int d = dg * 16 + j * 4;
            x_dup[d+0][t] = make_float2(v.x, v.x);
            x_dup[d+1][t] = make_float2(v.y, v.y);
            x_dup[d+2][t] = make_float2(v.z, v.z);
            x_dup[d+3][t] = make_float2(v.w, v.w);
        }
    }
    for (int i = tid; i < DD*DD; i += 256)
        ((float*)W_sm)[i] = W[s*DD*DD + i];
    __syncthreads();

    // ---- B) proj GEMM (f32x2): 4 tokens x 4 e per thread ----
    {
        const int ty = tid >> 4, tx = tid & 15;
        ULL a00=0,a01=0,a10=0,a11=0,a20=0,a21=0,a30=0,a31=0;
        #pragma unroll 8
        for (int d = 0; d < DD; ++d) {
            ulonglong2 xa = *(const ulonglong2*)&x_dup[d][ty*4];
            ulonglong2 xb = *(const ulonglong2*)&x_dup[d][ty*4+2];
            ulonglong2 wv = *(const ulonglong2*)&W_sm[d][tx*4];
            fma2(a00, xa.x, wv.x); fma2(a01, xa.x, wv.y);
            fma2(a10, xa.y, wv.x); fma2(a11, xa.y, wv.y);
            fma2(a20, xb.x, wv.x); fma2(a21, xb.x, wv.y);
            fma2(a30, xb.y, wv.x); fma2(a31, xb.y, wv.y);
        }
        // BN, reference op order
        float4 bi4 = *(const float4*)&bias[s*DD + tx*4];
        float4 gm4 = *(const float4*)&gamma[s*DD + tx*4];
        float4 bt4 = *(const float4*)&beta[s*DD + tx*4];
        float4 mn4 = *(const float4*)&bn_mean[s*DD + tx*4];
        float4 vr4 = *(const float4*)&bn_var[s*DD + tx*4];
        float inv0 = 1.0f / sqrtf(__fadd_rn(vr4.x, 1e-3f));
        float inv1 = 1.0f / sqrtf(__fadd_rn(vr4.y, 1e-3f));
        float inv2 = 1.0f / sqrtf(__fadd_rn(vr4.z, 1e-3f));
        float inv3 = 1.0f / sqrtf(__fadd_rn(vr4.w, 1e-3f));
        ULL accs[4][2] = {{a00,a01},{a10,a11},{a20,a21},{a30,a31}};
        #pragma unroll
        for (int i = 0; i < 4; ++i) {
            float2 p0 = unpk(accs[i][0]);
            float2 p1 = unpk(accs[i][1]);
            float* row = att[ty*4+i];
            float pv;
            pv = __fadd_rn(p0.x, bi4.x);
            row[tx*4+0] = __fadd_rn(__fmul_rn(__fmul_rn(gm4.x, __fsub_rn(pv, mn4.x)), inv0), bt4.x);
            pv = __fadd_rn(p0.y, bi4.y);
            row[tx*4+1] = __fadd_rn(__fmul_rn(__fmul_rn(gm4.y, __fsub_rn(pv, mn4.y)), inv1), bt4.y);
            pv = __fadd_rn(p1.x, bi4.z);
            row[tx*4+2] = __fadd_rn(__fmul_rn(__fmul_rn(gm4.z, __fsub_rn(pv, mn4.z)), inv2), bt4.z);
            pv = __fadd_rn(p1.y, bi4.w);
            row[tx*4+3] = __fadd_rn(__fmul_rn(__fmul_rn(gm4.w, __fsub_rn(pv, mn4.w)), inv3), bt4.w);
        }
    }
    __syncthreads();

    // ---- C) softmax + z (4 threads / token), write z to scratch ----
    {
        const int t = tid >> 2, q = tid & 3;
        float ev[16];
        float m = -INFINITY;
        #pragma unroll
        for (int j = 0; j < 16; ++j) { ev[j] = att[t][q*16 + j]; m = fmaxf(m, ev[j]); }
        m = fmaxf(m, __shfl_xor_sync(0xffffffffu, m, 1));
        m = fmaxf(m, __shfl_xor_sync(0xffffffffu, m, 2));
        float sum = 0.f;
        #pragma unroll
        for (int j = 0; j < 16; ++j) { ev[j] = expf(ev[j] - m); sum = __fadd_rn(sum, ev[j]); }
        sum = __fadd_rn(sum, __shfl_xor_sync(0xffffffffu, sum, 1));
        sum = __fadd_rn(sum, __shfl_xor_sync(0xffffffffu, sum, 2));
        float zn = 0.f;
        float zv[16];
        #pragma unroll
        for (int j = 0; j < 16; ++j) {
            float a = __fdiv_rn(ev[j], sum);
            float xx = x_dup[q*16 + j][t].x;
            float z = __fmul_rn(xx, a);
            zv[j] = z;
            z_dup[q*16 + j][t] = make_float2(z, z);
            zn = __fadd_rn(zn, __fmul_rn(z, z));
        }
        float* zp = g_z + ((size_t)s*NTOK + tok0 + t) * DD + q*16;
        #pragma unroll
        for (int j4 = 0; j4 < 4; ++j4)
            *(float4*)(zp + 4*j4) = make_float4(zv[4*j4], zv[4*j4+1], zv[4*j4+2], zv[4*j4+3]);
        zn = __fadd_rn(zn, __shfl_xor_sync(0xffffffffu, zn, 1));
        zn = __fadd_rn(zn, __shfl_xor_sync(0xffffffffu, zn, 2));
        if (q == 0) znorm[t] = zn;
    }
    __syncthreads();    // z ready; att/W dead -> region reusable as E_p

    // ---- D) codebook distance (f32x2): 8 tokens x 4 codes per thread ----
    const int w = tid >> 5, l = tid & 31;
    float best_v[8]; int best_i[8];
    #pragma unroll
    for (int i = 0; i < 8; ++i) { best_v[i] = INFINITY; best_i[i] = 0x7fffffff; }

    for (int c = 0; c < NCHUNK; ++c) {
        {
            const float4* src = (const float4*)(g_Epack + ((s*NCHUNK + c) << 12));
            float4* dst = (float4*)E_p;
            #pragma unroll
            for (int i = tid; i < 2048; i += 256) dst[i] = src[i];
            if (tid < CHUNK) En[tid] = g_Enorm[s*KK + c*CHUNK + tid];
        }
        __syncthreads();

        ULL acc[8][2];
        #pragma unroll
        for (int i = 0; i < 8; ++i) { acc[i][0] = 0ull; acc[i][1] = 0ull; }

        #pragma unroll 16
        for (int d = 0; d < DD; ++d) {
            ulonglong2 z0 = *(const ulonglong2*)&z_dup[d][w*8+0];
            ulonglong2 z1 = *(const ulonglong2*)&z_dup[d][w*8+2];
            ulonglong2 z2 = *(const ulonglong2*)&z_dup[d][w*8+4];
            ulonglong2 z3 = *(const ulonglong2*)&z_dup[d][w*8+6];
            ULL e0 = *(const ULL*)&E_p[d][l];
            ULL e1 = *(const ULL*)&E_p[d][l+32];
            fma2(acc[0][0], z0.x, e0); fma2(acc[0][1], z0.x, e1);
            fma2(acc[1][0], z0.y, e0); fma2(acc[1][1], z0.y, e1);
            fma2(acc[2][0], z1.x, e0); fma2(acc[2][1], z1.x, e1);
            fma2(acc[3][0], z1.y, e0); fma2(acc[3][1], z1.y, e1);
            fma2(acc[4][0], z2.x, e0); fma2(acc[4][1], z2.x, e1);
            fma2(acc[5][0], z2.y, e0); fma2(acc[5][1], z2.y, e1);
            fma2(acc[6][0], z3.x, e0); fma2(acc[6][1], z3.x, e1);
            fma2(acc[7][0], z3.y, e0); fma2(acc[7][1], z3.y, e1);
        }

        // epilogue: d2 = (||z||^2 - 2*dot) + ||E||^2 (reference association)
        float2 en0 = *(const float2*)&En[2*l];
        float2 en1 = *(const float2*)&En[2*l + 64];
        const int cb = c*CHUNK;
        #pragma unroll
        for (int i = 0; i < 8; ++i) {
            float zn = znorm[w*8 + i];
            float2 d0 = unpk(acc[i][0]);
            float2 d1 = unpk(acc[i][1]);
            float v;
            v = __fadd_rn(__fsub_rn(zn, 2.0f*d0.x), en0.x);
            if (v < best_v[i]) { best_v[i] = v; best_i[i] = cb + 2*l; }
            v = __fadd_rn(__fsub_rn(zn, 2.0f*d0.y), en0.y);
            if (v < best_v[i]) { best_v[i] = v; best_i[i] = cb + 2*l + 1; }
            v = __fadd_rn(__fsub_rn(zn, 2.0f*d1.x), en1.x);
            if (v < best_v[i]) { best_v[i] = v; best_i[i] = cb + 2*l + 64; }
            v = __fadd_rn(__fsub_rn(zn, 2.0f*d1.y), en1.y);
            if (v < best_v[i]) { best_v[i] = v; best_i[i] = cb + 2*l + 65; }
        }
        __syncthreads();
    }

    // ---- E) warp argmin reduction (first-occurrence => min index tie-break) ----
    #pragma unroll
    for (int i = 0; i < 8; ++i) {
        float v = best_v[i]; int bi = best_i[i];
        #pragma unroll
        for (int off = 16; off > 0; off >>= 1) {
            float ov = __shfl_xor_sync(0xffffffffu, v, off);
            int   oi = __shfl_xor_sync(0xffffffffu, bi, off);
            if (ov < v || (ov == v && oi < bi)) { v = ov; bi = oi; }
        }
        if (l == i)
            out[ZK_OFF + (size_t)s*NTOK + tok0 + w*8 + i] = (float)bi;
    }
    (void)kmin;
}

// ---- kernel2: z_e = sum_s z ; z_q = sum_s E[s, zk[s,t]] ----
__global__ __launch_bounds__(256)
void qlayer_k2(const float* __restrict__ E, float* __restrict__ out)
{
    int gid = blockIdx.x * blockDim.x + threadIdx.x;   // 65536 = NTOK*4
    const int t = gid >> 2, q = gid & 3;

    float ae[16], aq[16];
    #pragma unroll
    for (int j = 0; j < 16; ++j) { ae[j] = 0.f; aq[j] = 0.f; }

    #pragma unroll
    for (int s = 0; s < SS; ++s) {
        const float* zp = g_z + ((size_t)s*NTOK + t) * DD + q*16;
        #pragma unroll
        for (int j4 = 0; j4 < 4; ++j4) {
            float4 v = *(const float4*)(zp + 4*j4);
            ae[4*j4+0] = __fadd_rn(ae[4*j4+0], v.x);
            ae[4*j4+1] = __fadd_rn(ae[4*j4+1], v.y);
            ae[4*j4+2] = __fadd_rn(ae[4*j4+2], v.z);
            ae[4*j4+3] = __fadd_rn(ae[4*j4+3], v.w);
        }
        const int k = (int)out[ZK_OFF + (size_t)s*NTOK + t];
        const float* ep = E + ((size_t)s*KK + k) * DD + q*16;
        #pragma unroll
        for (int j4 = 0; j4 < 4; ++j4) {
            float4 v = *(const float4*)(ep + 4*j4);
            aq[4*j4+0] = __fadd_rn(aq[4*j4+0], v.x);
            aq[4*j4+1] = __fadd_rn(aq[4*j4+1], v.y);
            aq[4*j4+2] = __fadd_rn(aq[4*j4+2], v.z);
            aq[4*j4+3] = __fadd_rn(aq[4*j4+3], v.w);
        }
    }

    float* oq = out + ZQ_OFF + (size_t)t * DD + q*16;
    float* oe = out + ZE_OFF + (size_t)t * DD + q*16;
    #pragma unroll
    for (int j4 = 0; j4 < 4; ++j4) {
        *(float4*)(oq + 4*j4) = make_float4(aq[4*j4], aq[4*j4+1], aq[4*j4+2], aq[4*j4+3]);
        *(float4*)(oe + 4*j4) = make_float4(ae[4*j4], ae[4*j4+1], ae[4*j4+2], ae[4*j4+3]);
    }
}

extern "C" void kernel_launch(void* const* d_in, const int* in_sizes, int n_in,
                              void* d_out, int out_size)
{
    const float* x       = (const float*)d_in[0];
    const float* W       = (const float*)d_in[1];
    const float* b       = (const float*)d_in[2];
    const float* gamma   = (const float*)d_in[3];
    const float* beta    = (const float*)d_in[4];
    const float* bn_mean = (const float*)d_in[5];
    const float* bn_var  = (const float*)d_in[6];
    const float* E       = (const float*)d_in[7];
    float* out = (float*)d_out;

    // pack (131072 threads) + norms (4096 threads) in one wide launch
    prep_kernel<<<(NPACK + SS*KK + 255)/256, 256>>>(E);

    cudaFuncSetAttribute(qlayer_k1,
                         cudaFuncAttributeMaxDynamicSharedMemorySize, SMEM_BYTES);
    dim3 grid(NTOK/TPB, SS);     // 32 x 8 = 256... (tiles x slots) -> 2048 CTAs total
    qlayer_k1<<<dim3(NTOK/TPB, SS), 256, SMEM_BYTES>>>(x, W, b, gamma, beta,
                                                       bn_mean, bn_var, out);

    qlayer_k2<<<(NTOK*4)/256, 256>>>(E, out);
}

// round 6
// speedup vs baseline: 1.8553x; 1.0764x over previous
#include <cuda_runtime.h>
#include <math.h>

#define SS 8
#define DD 64
#define KK 512
#define NTOK 16384
#define TPB 64
#define CHUNK 128
#define NCHUNK 4
#define ZQ_OFF 0
#define ZE_OFF (NTOK*DD)          // 1048576
#define ZK_OFF (2*NTOK*DD)        // 2097152

typedef unsigned long long ULL;

__device__ float g_Enorm[SS*KK];
// lane-quad pack: [s][c][d][q], float4 = codes (c*128+4q .. +3) at dim d
__device__ __align__(16) float4 g_Epack4[SS*NCHUNK*DD*32];
// per-slot z scratch: [s][token][d]  (32 MB)
__device__ __align__(16) float g_z[(size_t)SS*NTOK*DD];

__device__ __forceinline__ void fma2(ULL& d, ULL a, ULL b) {
    asm("fma.rn.f32x2 %0, %1, %2, %3;" : "=l"(d) : "l"(a), "l"(b), "l"(d));
}
__device__ __forceinline__ float2 unpk(ULL v) {
    float lo, hi;
    asm("mov.b64 {%0,%1}, %2;" : "=f"(lo), "=f"(hi) : "l"(v));
    return make_float2(lo, hi);
}
__device__ __forceinline__ void cp16(void* sdst, const void* gsrc) {
    unsigned sa = (unsigned)__cvta_generic_to_shared(sdst);
    asm volatile("cp.async.cg.shared.global [%0], [%1], 16;" :: "r"(sa), "l"(gsrc));
}
#define CP_COMMIT() asm volatile("cp.async.commit_group;")
#define CP_WAIT(n)  asm volatile("cp.async.wait_group %0;" :: "n"(n))

// ---- prep: blocks [0,32) transpose-pack E via smem; blocks [32,48) norms ----
__global__ __launch_bounds__(256)
void prep_kernel(const float* __restrict__ E) {
    if (blockIdx.x < SS*NCHUNK) {
        __shared__ float tile[CHUNK][DD];     // 32 KB
        const int b = blockIdx.x;             // s*4 + c
        const float* base = E + (size_t)b * CHUNK * DD;   // (s*KK + c*128)*DD
        // coalesced load: 2048 float4
        for (int i = threadIdx.x; i < CHUNK*DD/4; i += 256) {
            int row = i >> 4, f4 = i & 15;
            float4 v = *(const float4*)(base + row*DD + f4*4);
            tile[row][f4*4+0] = v.x; tile[row][f4*4+1] = v.y;
            tile[row][f4*4+2] = v.z; tile[row][f4*4+3] = v.w;
        }
        __syncthreads();
        // coalesced pack store: j = d*32 + q
        for (int j = threadIdx.x; j < DD*32; j += 256) {
            int q = j & 31, d = j >> 5;
            g_Epack4[b*2048 + j] = make_float4(tile[4*q+0][d], tile[4*q+1][d],
                                               tile[4*q+2][d], tile[4*q+3][d]);
        }
    } else {
        // norms: block handles 256 rows, one per thread, sequential d-order rounding
        int row = (blockIdx.x - SS*NCHUNK) * 256 + threadIdx.x;   // < 4096
        const float* e = E + (size_t)row * DD;
        float4 v[16];
        #pragma unroll
        for (int j = 0; j < 16; ++j) v[j] = *(const float4*)(e + 4*j);
        float s = 0.f;
        #pragma unroll
        for (int j = 0; j < 16; ++j) {
            s = __fadd_rn(s, __fmul_rn(v[j].x, v[j].x));
            s = __fadd_rn(s, __fmul_rn(v[j].y, v[j].y));
            s = __fadd_rn(s, __fmul_rn(v[j].z, v[j].z));
            s = __fadd_rn(s, __fmul_rn(v[j].w, v[j].w));
        }
        g_Enorm[row] = s;
    }
}

// smem layout (99840 B):
//  +0      x_dup 32768      (reused as E buffer B in phase D)
//  +32768  z_dup 32768
//  +65536  region 33024     (W 16384 + att 16640; first 32768 reused as E buffer A)
//  +98560  EnA 512 | +99072 EnB 512 | +99584 znorm 256
#define SMEM_BYTES 99840

__device__ __forceinline__ void dist_chunk(
    const float2 (*z_dup)[TPB], const float4* __restrict__ EA,
    const float* __restrict__ En, const float* __restrict__ znorm,
    int w, int l, int cb, float* best_v, int* best_i)
{
    ULL acc[8][2];
    #pragma unroll
    for (int i = 0; i < 8; ++i) { acc[i][0] = 0ull; acc[i][1] = 0ull; }

    #pragma unroll 8
    for (int d = 0; d < DD; ++d) {
        ulonglong2 ee = *(const ulonglong2*)&EA[d*32 + l];
        ulonglong2 z0 = *(const ulonglong2*)&z_dup[d][w*8+0];
        ulonglong2 z1 = *(const ulonglong2*)&z_dup[d][w*8+2];
        ulonglong2 z2 = *(const ulonglong2*)&z_dup[d][w*8+4];
        ulonglong2 z3 = *(const ulonglong2*)&z_dup[d][w*8+6];
        fma2(acc[0][0], z0.x, ee.x); fma2(acc[0][1], z0.x, ee.y);
        fma2(acc[1][0], z0.y, ee.x); fma2(acc[1][1], z0.y, ee.y);
        fma2(acc[2][0], z1.x, ee.x); fma2(acc[2][1], z1.x, ee.y);
        fma2(acc[3][0], z1.y, ee.x); fma2(acc[3][1], z1.y, ee.y);
        fma2(acc[4][0], z2.x, ee.x); fma2(acc[4][1], z2.x, ee.y);
        fma2(acc[5][0], z2.y, ee.x); fma2(acc[5][1], z2.y, ee.y);
        fma2(acc[6][0], z3.x, ee.x); fma2(acc[6][1], z3.x, ee.y);
        fma2(acc[7][0], z3.y, ee.x); fma2(acc[7][1], z3.y, ee.y);
    }

    float4 en = *(const float4*)&En[4*l];
    #pragma unroll
    for (int i = 0; i < 8; ++i) {
        float zn = znorm[w*8 + i];
        float2 d0 = unpk(acc[i][0]);
        float2 d1 = unpk(acc[i][1]);
        float v;
        // (zn - 2*dot) + En ; fma(-2,dot,zn) == fsub(zn, 2*dot) since 2*dot exact
        v = __fadd_rn(__fmaf_rn(-2.f, d0.x, zn), en.x);
        if (v < best_v[i]) { best_v[i] = v; best_i[i] = cb + 4*l + 0; }
        v = __fadd_rn(__fmaf_rn(-2.f, d0.y, zn), en.y);
        if (v < best_v[i]) { best_v[i] = v; best_i[i] = cb + 4*l + 1; }
        v = __fadd_rn(__fmaf_rn(-2.f, d1.x, zn), en.z);
        if (v < best_v[i]) { best_v[i] = v; best_i[i] = cb + 4*l + 2; }
        v = __fadd_rn(__fmaf_rn(-2.f, d1.y, zn), en.w);
        if (v < best_v[i]) { best_v[i] = v; best_i[i] = cb + 4*l + 3; }
    }
}

__global__ __launch_bounds__(256, 2)
void qlayer_k1(const float* __restrict__ x,
               const float* __restrict__ W,
               const float* __restrict__ bias,
               const float* __restrict__ gamma,
               const float* __restrict__ beta,
               const float* __restrict__ bn_mean,
               const float* __restrict__ bn_var,
               float* __restrict__ out)
{
    extern __shared__ char smraw[];
    float2 (*x_dup)[TPB] = (float2(*)[TPB])smraw;
    float2 (*z_dup)[TPB] = (float2(*)[TPB])(smraw + 32768);
    char*  region        = smraw + 65536;
    float  (*W_sm)[DD]   = (float(*)[DD])region;
    float  (*att)[DD+1]  = (float(*)[DD+1])(region + 16384);
    float4* EA   = (float4*)region;             // buffer A (aliases W+att)
    float4* EB   = (float4*)smraw;              // buffer B (aliases x_dup)
    float* EnA   = (float*)(smraw + 98560);
    float* EnB   = (float*)(smraw + 99072);
    float* znorm = (float*)(smraw + 99584);

    const int tid  = threadIdx.x;
    const int tok0 = blockIdx.x * TPB;
    const int s    = blockIdx.y;

    // ---- load x tile duplicated-transposed; W in parallel ----
    {
        const int t = tid & 63, dg = tid >> 6;
        const float* xp = x + (size_t)(tok0 + t) * DD + dg * 16;
        #pragma unroll
        for (int j = 0; j < 4; ++j) {
            float4 v = *(const float4*)(xp + j * 4);
            int d = dg * 16 + j * 4;
            x_dup[d+0][t] = make_float2(v.x, v.x);
            x_dup[d+1][t] = make_float2(v.y, v.y);
            x_dup[d+2][t] = make_float2(v.z, v.z);
            x_dup[d+3][t] = make_float2(v.w, v.w);
        }
    }
    for (int i = tid; i < DD*DD; i += 256)
        ((float*)W_sm)[i] = W[s*DD*DD + i];
    __syncthreads();

    // ---- proj GEMM (f32x2): 4 tokens x 4 e per thread ----
    {
        const int ty = tid >> 4, tx = tid & 15;
        ULL a00=0,a01=0,a10=0,a11=0,a20=0,a21=0,a30=0,a31=0;
        #pragma unroll 8
        for (int d = 0; d < DD; ++d) {
            ulonglong2 xa = *(const ulonglong2*)&x_dup[d][ty*4];
            ulonglong2 xb = *(const ulonglong2*)&x_dup[d][ty*4+2];
            ulonglong2 wv = *(const ulonglong2*)&W_sm[d][tx*4];
            fma2(a00, xa.x, wv.x); fma2(a01, xa.x, wv.y);
            fma2(a10, xa.y, wv.x); fma2(a11, xa.y, wv.y);
            fma2(a20, xb.x, wv.x); fma2(a21, xb.x, wv.y);
            fma2(a30, xb.y, wv.x); fma2(a31, xb.y, wv.y);
        }
        float4 bi4 = *(const float4*)&bias[s*DD + tx*4];
        float4 gm4 = *(const float4*)&gamma[s*DD + tx*4];
        float4 bt4 = *(const float4*)&beta[s*DD + tx*4];
        float4 mn4 = *(const float4*)&bn_mean[s*DD + tx*4];
        float4 vr4 = *(const float4*)&bn_var[s*DD + tx*4];
        float inv0 = 1.0f / sqrtf(__fadd_rn(vr4.x, 1e-3f));
        float inv1 = 1.0f / sqrtf(__fadd_rn(vr4.y, 1e-3f));
        float inv2 = 1.0f / sqrtf(__fadd_rn(vr4.z, 1e-3f));
        float inv3 = 1.0f / sqrtf(__fadd_rn(vr4.w, 1e-3f));
        ULL accs[4][2] = {{a00,a01},{a10,a11},{a20,a21},{a30,a31}};
        #pragma unroll
        for (int i = 0; i < 4; ++i) {
            float2 p0 = unpk(accs[i][0]);
            float2 p1 = unpk(accs[i][1]);
            float* row = att[ty*4+i];
            float pv;
            pv = __fadd_rn(p0.x, bi4.x);
            row[tx*4+0] = __fadd_rn(__fmul_rn(__fmul_rn(gm4.x, __fsub_rn(pv, mn4.x)), inv0), bt4.x);
            pv = __fadd_rn(p0.y, bi4.y);
            row[tx*4+1] = __fadd_rn(__fmul_rn(__fmul_rn(gm4.y, __fsub_rn(pv, mn4.y)), inv1), bt4.y);
            pv = __fadd_rn(p1.x, bi4.z);
            row[tx*4+2] = __fadd_rn(__fmul_rn(__fmul_rn(gm4.z, __fsub_rn(pv, mn4.z)), inv2), bt4.z);
            pv = __fadd_rn(p1.y, bi4.w);
            row[tx*4+3] = __fadd_rn(__fmul_rn(__fmul_rn(gm4.w, __fsub_rn(pv, mn4.w)), inv3), bt4.w);
        }
    }
    __syncthreads();

    // ---- softmax + z (4 threads/token), write z to scratch ----
    {
        const int t = tid >> 2, q = tid & 3;
        float ev[16];
        float m = -INFINITY;
        #pragma unroll
        for (int j = 0; j < 16; ++j) { ev[j] = att[t][q*16 + j]; m = fmaxf(m, ev[j]); }
        m = fmaxf(m, __shfl_xor_sync(0xffffffffu, m, 1));
        m = fmaxf(m, __shfl_xor_sync(0xffffffffu, m, 2));
        float sum = 0.f;
        #pragma unroll
        for (int j = 0; j < 16; ++j) { ev[j] = expf(ev[j] - m); sum = __fadd_rn(sum, ev[j]); }
        sum = __fadd_rn(sum, __shfl_xor_sync(0xffffffffu, sum, 1));
        sum = __fadd_rn(sum, __shfl_xor_sync(0xffffffffu, sum, 2));
        float zn = 0.f;
        float zv[16];
        #pragma unroll
        for (int j = 0; j < 16; ++j) {
            float a = __fdiv_rn(ev[j], sum);
            float xx = x_dup[q*16 + j][t].x;
            float z = __fmul_rn(xx, a);
            zv[j] = z;
            z_dup[q*16 + j][t] = make_float2(z, z);
            zn = __fadd_rn(zn, __fmul_rn(z, z));
        }
        float* zp = g_z + ((size_t)s*NTOK + tok0 + t) * DD + q*16;
        #pragma unroll
        for (int j4 = 0; j4 < 4; ++j4)
            *(float4*)(zp + 4*j4) = make_float4(zv[4*j4], zv[4*j4+1], zv[4*j4+2], zv[4*j4+3]);
        zn = __fadd_rn(zn, __shfl_xor_sync(0xffffffffu, zn, 1));
        zn = __fadd_rn(zn, __shfl_xor_sync(0xffffffffu, zn, 2));
        if (q == 0) znorm[t] = zn;
    }
    __syncthreads();    // z ready; x/W/att dead -> both E buffers usable

    // ---- codebook distance, cp.async double-buffered over 4 chunks ----
    const int w = tid >> 5, l = tid & 31;
    float best_v[8]; int best_i[8];
    #pragma unroll
    for (int i = 0; i < 8; ++i) { best_v[i] = INFINITY; best_i[i] = 0x7fffffff; }

    const float4* esrc = g_Epack4 + (size_t)(s*NCHUNK) * 2048;
    const float*  ensrc = g_Enorm + s*KK;

    // issue chunk c into buffer/En
    #define ISSUE(c, BUF, ENB) do {                                     \
        const float4* _src = esrc + (c)*2048;                           \
        _Pragma("unroll")                                               \
        for (int _i = tid; _i < 2048; _i += 256)                        \
            cp16(&(BUF)[_i], &_src[_i]);                                \
        if (tid < 32) cp16((float4*)(ENB) + tid,                        \
                           (const float4*)(ensrc + (c)*CHUNK) + tid);   \
        CP_COMMIT();                                                    \
    } while (0)

    ISSUE(0, EA, EnA);
    ISSUE(1, EB, EnB);

    CP_WAIT(1); __syncthreads();
    dist_chunk(z_dup, EA, EnA, znorm, w, l, 0*CHUNK, best_v, best_i);
    __syncthreads();
    ISSUE(2, EA, EnA);

    CP_WAIT(1); __syncthreads();
    dist_chunk(z_dup, EB, EnB, znorm, w, l, 1*CHUNK, best_v, best_i);
    __syncthreads();
    ISSUE(3, EB, EnB);

    CP_WAIT(1); __syncthreads();
    dist_chunk(z_dup, EA, EnA, znorm, w, l, 2*CHUNK, best_v, best_i);

    CP_WAIT(0); __syncthreads();
    dist_chunk(z_dup, EB, EnB, znorm, w, l, 3*CHUNK, best_v, best_i);
    #undef ISSUE

    // ---- warp argmin reduction (first-occurrence => min index tie-break) ----
    #pragma unroll
    for (int i = 0; i < 8; ++i) {
        float v = best_v[i]; int bi = best_i[i];
        #pragma unroll
        for (int off = 16; off > 0; off >>= 1) {
            float ov = __shfl_xor_sync(0xffffffffu, v, off);
            int   oi = __shfl_xor_sync(0xffffffffu, bi, off);
            if (ov < v || (ov == v && oi < bi)) { v = ov; bi = oi; }
        }
        if (l == i)
            out[ZK_OFF + (size_t)s*NTOK + tok0 + w*8 + i] = (float)bi;
    }
}

// ---- kernel2: z_e = sum_s z ; z_q = sum_s E[s, zk[s,t]] ----
__global__ __launch_bounds__(256)
void qlayer_k2(const float* __restrict__ E, float* __restrict__ out)
{
    int gid = blockIdx.x * blockDim.x + threadIdx.x;
    const int t = gid >> 2, q = gid & 3;

    float ae[16], aq[16];
    #pragma unroll
    for (int j = 0; j < 16; ++j) { ae[j] = 0.f; aq[j] = 0.f; }

    #pragma unroll
    for (int s = 0; s < SS; ++s) {
        const float* zp = g_z + ((size_t)s*NTOK + t) * DD + q*16;
        #pragma unroll
        for (int j4 = 0; j4 < 4; ++j4) {
            float4 v = *(const float4*)(zp + 4*j4);
            ae[4*j4+0] = __fadd_rn(ae[4*j4+0], v.x);
            ae[4*j4+1] = __fadd_rn(ae[4*j4+1], v.y);
            ae[4*j4+2] = __fadd_rn(ae[4*j4+2], v.z);
            ae[4*j4+3] = __fadd_rn(ae[4*j4+3], v.w);
        }
        const int k = (int)out[ZK_OFF + (size_t)s*NTOK + t];
        const float* ep = E + ((size_t)s*KK + k) * DD + q*16;
        #pragma unroll
        for (int j4 = 0; j4 < 4; ++j4) {
            float4 v = *(const float4*)(ep + 4*j4);
            aq[4*j4+0] = __fadd_rn(aq[4*j4+0], v.x);
            aq[4*j4+1] = __fadd_rn(aq[4*j4+1], v.y);
            aq[4*j4+2] = __fadd_rn(aq[4*j4+2], v.z);
            aq[4*j4+3] = __fadd_rn(aq[4*j4+3], v.w);
        }
    }

    float* oq = out + ZQ_OFF + (size_t)t * DD + q*16;
    float* oe = out + ZE_OFF + (size_t)t * DD + q*16;
    #pragma unroll
    for (int j4 = 0; j4 < 4; ++j4) {
        *(float4*)(oq + 4*j4) = make_float4(aq[4*j4], aq[4*j4+1], aq[4*j4+2], aq[4*j4+3]);
        *(float4*)(oe + 4*j4) = make_float4(ae[4*j4], ae[4*j4+1], ae[4*j4+2], ae[4*j4+3]);
    }
}

extern "C" void kernel_launch(void* const* d_in, const int* in_sizes, int n_in,
                              void* d_out, int out_size)
{
    const float* x       = (const float*)d_in[0];
    const float* W       = (const float*)d_in[1];
    const float* b       = (const float*)d_in[2];
    const float* gamma   = (const float*)d_in[3];
    const float* beta    = (const float*)d_in[4];
    const float* bn_mean = (const float*)d_in[5];
    const float* bn_var  = (const float*)d_in[6];
    const float* E       = (const float*)d_in[7];
    float* out = (float*)d_out;

    prep_kernel<<<SS*NCHUNK + 16, 256>>>(E);

    cudaFuncSetAttribute(qlayer_k1,
                         cudaFuncAttributeMaxDynamicSharedMemorySize, SMEM_BYTES);
    qlayer_k1<<<dim3(NTOK/TPB, SS), 256, SMEM_BYTES>>>(x, W, b, gamma, beta,
                                                       bn_mean, bn_var, out);

    qlayer_k2<<<(NTOK*4)/256, 256>>>(E, out);
}